// round 7
// baseline (speedup 1.0000x reference)
#include <cuda_runtime.h>

#define NNODES 100000
#define NEDGES 3200000
#define INCH 128
#define HID 64
#define SCAN_B 1024

// ---------------- scratch (static device globals; no allocs allowed) ----------------
__device__ float d_g[(size_t)NNODES * HID];    // dinv-scaled features (gather source)
__device__ float d_h[(size_t)NNODES * HID];    // layer intermediate
__device__ float d_dinv[NNODES];
__device__ int   d_cnt[NNODES];                // in-degree (excl self loop)
__device__ int   d_off[NNODES + 1];            // CSR offsets
__device__ int   d_cur[NNODES];                // placement cursors
__device__ int   d_bsum[256];                  // per-block scan partials
__device__ int   d_srcs[NEDGES];               // CSR: source node per incoming edge
__device__ int   d_eid[NEDGES];                // CSR: original edge id
__device__ int   d_ecol[NEDGES];               // CSR: dest node per position
__device__ int   d_row[NEDGES];
__device__ int   d_col[NEDGES];
__device__ int   g_idx64;

// ---------------- helpers ----------------
__device__ __forceinline__ unsigned long long pack2(float v) {
    unsigned long long r;
    asm("mov.b64 %0, {%1, %1};" : "=l"(r) : "f"(v));
    return r;
}
__device__ __forceinline__ void fma2(unsigned long long& acc, unsigned long long a,
                                     unsigned long long b) {
    asm("fma.rn.f32x2 %0, %1, %2, %0;" : "+l"(acc) : "l"(a), "l"(b));
}
__device__ __forceinline__ float2 unpack2(unsigned long long v) {
    float2 r;
    asm("mov.b64 {%0, %1}, %2;" : "=f"(r.x), "=f"(r.y) : "l"(v));
    return r;
}

// ---------------- dtype detection: int64 edge_index has zero high words --------------
__global__ void detect_kernel(const unsigned* __restrict__ ei) {
    unsigned v = 0;
    int i = threadIdx.x;
#pragma unroll
    for (int s = 0; s < 4; ++s) v |= ei[(size_t)(i * 4 + s) * 2 + 1];
    unsigned any = __ballot_sync(0xffffffffu, v != 0);
    if (threadIdx.x == 0) g_idx64 = (any == 0) ? 1 : 0;
}

__global__ void init_cnt_kernel(int n) {
    int i = blockIdx.x * blockDim.x + threadIdx.x;
    if (i < n) d_cnt[i] = 0;
}

// ---------------- convert (int64/int32 -> int32) + in-degree histogram fused --------
__global__ void convert_kernel(const void* __restrict__ ei, int E) {
    int i = blockIdx.x * blockDim.x + threadIdx.x;
    if (i >= E) return;
    int r, c;
    if (g_idx64) {
        const long long* p = (const long long*)ei;
        r = (int)p[i];
        c = (int)p[(size_t)E + i];
    } else {
        const int* p = (const int*)ei;
        r = p[i];
        c = p[(size_t)E + i];
    }
    d_row[i] = r;
    d_col[i] = c;
    atomicAdd(&d_cnt[c], 1);
}

// ---------------- multi-block exclusive scan: 3 phases -------------------------------
__global__ __launch_bounds__(SCAN_B) void scan1_kernel(int n) {
    __shared__ int swarp[32];
    int t = threadIdx.x, lane = t & 31, wid = t >> 5;
    int i = blockIdx.x * SCAN_B + t;
    int v = (i < n) ? d_cnt[i] : 0;
    int incl = v;
#pragma unroll
    for (int o = 1; o < 32; o <<= 1) {
        int x = __shfl_up_sync(0xffffffffu, incl, o);
        if (lane >= o) incl += x;
    }
    if (lane == 31) swarp[wid] = incl;
    __syncthreads();
    if (wid == 0) {
        int wv = swarp[lane];
        int winc = wv;
#pragma unroll
        for (int o = 1; o < 32; o <<= 1) {
            int x = __shfl_up_sync(0xffffffffu, winc, o);
            if (lane >= o) winc += x;
        }
        swarp[lane] = winc - wv;
        if (lane == 31) d_bsum[blockIdx.x] = winc;
    }
    __syncthreads();
    if (i < n) d_off[i] = incl - v + swarp[wid];
}

__global__ void scan2_kernel(int nb) {
    __shared__ int swarp[32];
    int t = threadIdx.x, lane = t & 31, wid = t >> 5; // 256 threads
    int v = (t < nb) ? d_bsum[t] : 0;
    int incl = v;
#pragma unroll
    for (int o = 1; o < 32; o <<= 1) {
        int x = __shfl_up_sync(0xffffffffu, incl, o);
        if (lane >= o) incl += x;
    }
    if (lane == 31) swarp[wid] = incl;
    __syncthreads();
    if (wid == 0) {
        int wv = (lane < 8) ? swarp[lane] : 0;
        int winc = wv;
#pragma unroll
        for (int o = 1; o < 8; o <<= 1) {
            int x = __shfl_up_sync(0xffffffffu, winc, o);
            if (lane >= o) winc += x;
        }
        swarp[lane] = winc - wv;
    }
    __syncthreads();
    if (t < nb) d_bsum[t] = incl - v + swarp[wid];
}

__global__ __launch_bounds__(SCAN_B) void scan3_kernel(int n, int E) {
    int i = blockIdx.x * SCAN_B + threadIdx.x;
    if (i >= n) return;
    int excl = d_off[i] + d_bsum[blockIdx.x];
    d_off[i] = excl;
    d_cur[i] = excl;
    d_dinv[i] = rsqrtf((float)(d_cnt[i] + 1));
    if (i == n - 1) d_off[n] = E;
}

// ---------------- place edges into CSR (srcs + eid + ecol) --------------------------
__global__ void place_kernel(int E) {
    int i = blockIdx.x * blockDim.x + threadIdx.x;
    if (i >= E) return;
    int c = d_col[i];
    int pos = atomicAdd(&d_cur[c], 1);
    d_srcs[pos] = d_row[i];
    d_eid[pos]  = i;
    d_ecol[pos] = c;
}

// ---------------- GEMM: C[i,:] = act( (A[i,:] @ W)*(SCALE?dinv[i]:1) + (BIAS?b:0) ) --
template<int K, int NC, bool RELU, bool BIAS, bool SCALE, int R>
__global__ __launch_bounds__(256) void gemm_kernel(
    const float* __restrict__ A, const float* __restrict__ W,
    const float* __restrict__ bias, float* __restrict__ C, int nrows) {
    constexpr int CG  = NC / 16;
    constexpr int RPB = (256 / CG) * R;
    __shared__ float Ws[K * NC];
    for (int t = threadIdx.x; t < K * NC / 4; t += 256)
        ((float4*)Ws)[t] = ((const float4*)W)[t];
    __syncthreads();

    int rg = threadIdx.x / CG;
    int cg = threadIdx.x % CG;
    int r0 = blockIdx.x * RPB + rg * R;

    const float4* Arow[R];
    bool valid[R];
#pragma unroll
    for (int i = 0; i < R; ++i) {
        int r = r0 + i;
        valid[i] = (r < nrows);
        Arow[i] = (const float4*)(A + (size_t)(valid[i] ? r : 0) * K);
    }

    unsigned long long acc[R][8];
#pragma unroll
    for (int i = 0; i < R; ++i)
#pragma unroll
        for (int j = 0; j < 8; ++j) acc[i][j] = 0ull;

#pragma unroll
    for (int k4 = 0; k4 < K / 4; ++k4) {
        float4 a4[R];
#pragma unroll
        for (int i = 0; i < R; ++i) a4[i] = Arow[i][k4];
#pragma unroll
        for (int s = 0; s < 4; ++s) {
            int k = k4 * 4 + s;
            const unsigned long long* w2 =
                (const unsigned long long*)&Ws[k * NC + cg * 16];
            unsigned long long wr[8];
#pragma unroll
            for (int j = 0; j < 8; ++j) wr[j] = w2[j];
#pragma unroll
            for (int i = 0; i < R; ++i) {
                float av = (s == 0) ? a4[i].x : (s == 1) ? a4[i].y
                         : (s == 2) ? a4[i].z : a4[i].w;
                unsigned long long ap = pack2(av);
#pragma unroll
                for (int j = 0; j < 8; ++j) fma2(acc[i][j], ap, wr[j]);
            }
        }
    }

#pragma unroll
    for (int i = 0; i < R; ++i) {
        if (!valid[i]) continue;
        int r = r0 + i;
        float sc = SCALE ? d_dinv[r] : 1.0f;
        float4* Crow = (float4*)(C + (size_t)r * NC + cg * 16);
#pragma unroll
        for (int q = 0; q < 4; ++q) {
            float2 p0 = unpack2(acc[i][q * 2]);
            float2 p1 = unpack2(acc[i][q * 2 + 1]);
            float4 o = make_float4(p0.x * sc, p0.y * sc, p1.x * sc, p1.y * sc);
            if (BIAS) {
                const float4 bb = *(const float4*)&bias[cg * 16 + q * 4];
                o.x += bb.x; o.y += bb.y; o.z += bb.z; o.w += bb.w;
            }
            if (RELU) {
                o.x = fmaxf(o.x, 0.f); o.y = fmaxf(o.y, 0.f);
                o.z = fmaxf(o.z, 0.f); o.w = fmaxf(o.w, 0.f);
            }
            Crow[q] = o;
        }
    }
}

// ---------------- CSR gather: out[c] = relu(dinv[c]*(sum_in g[r] + g[c]) + b) --------
// One warp per node; each lane owns 2 feature columns (float2); 4-edge unroll for MLP.
__global__ __launch_bounds__(256) void gather_csr_kernel(
    const float* __restrict__ b, float* __restrict__ out, int n) {
    int warp = (blockIdx.x * blockDim.x + threadIdx.x) >> 5;
    if (warp >= n) return;
    int lane = threadIdx.x & 31;
    int start = d_off[warp];
    int end   = d_off[warp + 1];
    int col2  = lane * 2;

    float2 acc0 = make_float2(0.f, 0.f), acc1 = make_float2(0.f, 0.f);
    int p = start;
    for (; p + 3 < end; p += 4) {
        int r0 = d_srcs[p];
        int r1 = d_srcs[p + 1];
        int r2 = d_srcs[p + 2];
        int r3 = d_srcs[p + 3];
        float2 v0 = __ldcg((const float2*)&d_g[(size_t)r0 * HID + col2]);
        float2 v1 = __ldcg((const float2*)&d_g[(size_t)r1 * HID + col2]);
        float2 v2 = __ldcg((const float2*)&d_g[(size_t)r2 * HID + col2]);
        float2 v3 = __ldcg((const float2*)&d_g[(size_t)r3 * HID + col2]);
        acc0.x += v0.x; acc0.y += v0.y;
        acc1.x += v1.x; acc1.y += v1.y;
        acc0.x += v2.x; acc0.y += v2.y;
        acc1.x += v3.x; acc1.y += v3.y;
    }
    for (; p < end; ++p) {
        int r0 = d_srcs[p];
        float2 v0 = __ldcg((const float2*)&d_g[(size_t)r0 * HID + col2]);
        acc0.x += v0.x; acc0.y += v0.y;
    }
    // self loop + epilogue
    float2 gs = *(const float2*)&d_g[(size_t)warp * HID + col2];
    float di = d_dinv[warp];
    float2 bb = *(const float2*)&b[col2];
    float2 o;
    o.x = fmaxf(di * (acc0.x + acc1.x + gs.x) + bb.x, 0.f);
    o.y = fmaxf(di * (acc0.y + acc1.y + gs.y) + bb.y, 0.f);
    *(float2*)&out[(size_t)warp * HID + col2] = o;
}

// ---------------- edge scores in CSR order: c-side hits L1 (same col repeats) -------
// 16 lanes per CSR-position pair (2p, 2p+1): adjacent positions share the dest node.
__global__ void escore_csr_kernel(const float* __restrict__ nr,
                                  float* __restrict__ es, int E) {
    int tid = blockIdx.x * blockDim.x + threadIdx.x;
    int p0 = (tid >> 4) * 2;
    if (p0 >= E) return;
    int l = (tid & 15) * 4;
    int p1 = p0 + 1;
    bool has2 = (p1 < E);

    int r0 = d_srcs[p0], c0 = d_ecol[p0], e0 = d_eid[p0];
    int r1 = has2 ? d_srcs[p1] : 0;
    int c1 = has2 ? d_ecol[p1] : 0;
    int e1 = has2 ? d_eid[p1] : 0;

    float4 a0 = __ldcg((const float4*)&nr[(size_t)r0 * HID + l]);
    float4 b0 = __ldg((const float4*)&nr[(size_t)c0 * HID + l]);   // L1-resident
    float4 a1, b1;
    if (has2) {
        a1 = __ldcg((const float4*)&nr[(size_t)r1 * HID + l]);
        b1 = __ldg((const float4*)&nr[(size_t)c1 * HID + l]);      // L1-resident
    }
    float s0 = a0.x * b0.x + a0.y * b0.y + a0.z * b0.z + a0.w * b0.w;
    float s1 = has2 ? (a1.x * b1.x + a1.y * b1.y + a1.z * b1.z + a1.w * b1.w) : 0.f;
#pragma unroll
    for (int m = 8; m >= 1; m >>= 1) {
        s0 += __shfl_xor_sync(0xffffffffu, s0, m);
        s1 += __shfl_xor_sync(0xffffffffu, s1, m);
    }
    if ((tid & 15) == 0) {
        es[e0] = s0;
        if (has2) es[e1] = s1;
    }
}

// ---------------- launch ----------------
extern "C" void kernel_launch(void* const* d_in, const int* in_sizes, int n_in,
                              void* d_out, int out_size) {
    const float* x   = (const float*)d_in[0];
    const void*  ei  = d_in[1];
    const float* W1  = (const float*)d_in[2];
    const float* b1  = (const float*)d_in[3];
    const float* W2  = (const float*)d_in[4];
    const float* b2  = (const float*)d_in[5];
    const float* Wd1 = (const float*)d_in[6];
    const float* bd1 = (const float*)d_in[7];
    const float* Wd2 = (const float*)d_in[8];
    const float* bd2 = (const float*)d_in[9];
    float* out = (float*)d_out;

    int Nn = in_sizes[0] / INCH; // 100000
    int Ee = in_sizes[1] / 2;    // 3200000
    int half = (Ee + 1) / 2;

    float* out_rx = out;
    float* out_es = out + (size_t)Nn * INCH;
    float* out_nr = out_es + (size_t)Ee;

    float *pg = nullptr, *ph = nullptr;
    cudaGetSymbolAddress((void**)&pg, d_g);
    cudaGetSymbolAddress((void**)&ph, d_h);

    const int T = 256;
    int ebl   = (Ee + T - 1) / T;
    int nbl   = (Nn + T - 1) / T;
    int h16bl = (int)(((size_t)half * 16 + T - 1) / T);
    int nwbl  = (int)(((size_t)Nn * 32 + T - 1) / T); // warp per node
    int sbl   = (Nn + SCAN_B - 1) / SCAN_B;           // scan blocks (98)

    // preprocessing: convert+histogram -> 3-phase scan -> place
    detect_kernel<<<1, 32>>>((const unsigned*)ei);
    init_cnt_kernel<<<nbl, T>>>(Nn);
    convert_kernel<<<ebl, T>>>(ei, Ee);
    scan1_kernel<<<sbl, SCAN_B>>>(Nn);
    scan2_kernel<<<1, 256>>>(sbl);
    scan3_kernel<<<sbl, SCAN_B>>>(Nn, Ee);
    place_kernel<<<ebl, T>>>(Ee);

    // ---- layer 1: g = (x@W1)*dinv ; h = relu(dinv*(csr_sum(g)+g)+b1)
    gemm_kernel<INCH, HID, false, false, true, 4>
        <<<(Nn + 255) / 256, T>>>(x, W1, nullptr, pg, Nn);
    gather_csr_kernel<<<nwbl, T>>>(b1, ph, Nn);

    // ---- layer 2 -> node_representation (written straight into out segment)
    gemm_kernel<HID, HID, false, false, true, 4>
        <<<(Nn + 255) / 256, T>>>(ph, W2, nullptr, pg, Nn);
    gather_csr_kernel<<<nwbl, T>>>(b2, out_nr, Nn);

    // ---- decoder: rec = relu(nr@Wd1+bd1) ; rx = rec@Wd2 + bd2
    gemm_kernel<HID, HID, true, true, false, 4>
        <<<(Nn + 255) / 256, T>>>(out_nr, Wd1, bd1, ph, Nn);
    gemm_kernel<HID, INCH, false, true, false, 4>
        <<<(Nn + 127) / 128, T>>>(ph, Wd2, bd2, out_rx, Nn);

    // ---- edge scores (CSR order: dest-side rows hit L1)
    escore_csr_kernel<<<h16bl, T>>>(out_nr, out_es, Ee);
}

// round 8
// speedup vs baseline: 1.1206x; 1.1206x over previous
#include <cuda_runtime.h>

#define NNODES 100000
#define NEDGES 3200000
#define INCH 128
#define HID 64
#define SCAN_B 1024

// ---------------- scratch (static device globals; no allocs allowed) ----------------
__device__ float d_g[(size_t)NNODES * HID];    // dinv-scaled features (gather source)
__device__ float d_h[(size_t)NNODES * HID];    // layer intermediate
__device__ float d_dinv[NNODES];
__device__ int   d_cnt[NNODES];                // in-degree (excl self loop)
__device__ int   d_off[NNODES + 1];            // CSR offsets
__device__ int   d_cur[NNODES];                // placement cursors
__device__ int   d_bsum[256];                  // per-block scan partials
__device__ int   d_srcs[NEDGES];               // CSR: source node per incoming edge
__device__ int   d_row[NEDGES];
__device__ int   d_col[NEDGES];
__device__ int   g_idx64;

// ---------------- side stream + events for fork/join (created once, host-side) ------
struct SideCtx {
    cudaStream_t side;
    cudaEvent_t evA, evB, evC, evD;
    SideCtx() {
        cudaStreamCreateWithFlags(&side, cudaStreamNonBlocking);
        cudaEventCreateWithFlags(&evA, cudaEventDisableTiming);
        cudaEventCreateWithFlags(&evB, cudaEventDisableTiming);
        cudaEventCreateWithFlags(&evC, cudaEventDisableTiming);
        cudaEventCreateWithFlags(&evD, cudaEventDisableTiming);
    }
};
static SideCtx g_ctx;

// ---------------- helpers ----------------
__device__ __forceinline__ unsigned long long pack2(float v) {
    unsigned long long r;
    asm("mov.b64 %0, {%1, %1};" : "=l"(r) : "f"(v));
    return r;
}
__device__ __forceinline__ void fma2(unsigned long long& acc, unsigned long long a,
                                     unsigned long long b) {
    asm("fma.rn.f32x2 %0, %1, %2, %0;" : "+l"(acc) : "l"(a), "l"(b));
}
__device__ __forceinline__ float2 unpack2(unsigned long long v) {
    float2 r;
    asm("mov.b64 {%0, %1}, %2;" : "=f"(r.x), "=f"(r.y) : "l"(v));
    return r;
}

// ---------------- dtype detection: int64 edge_index has zero high words --------------
__global__ void detect_kernel(const unsigned* __restrict__ ei) {
    unsigned v = 0;
    int i = threadIdx.x;
#pragma unroll
    for (int s = 0; s < 4; ++s) v |= ei[(size_t)(i * 4 + s) * 2 + 1];
    unsigned any = __ballot_sync(0xffffffffu, v != 0);
    if (threadIdx.x == 0) g_idx64 = (any == 0) ? 1 : 0;
}

__global__ void init_cnt_kernel(int n) {
    int i = blockIdx.x * blockDim.x + threadIdx.x;
    if (i < n) d_cnt[i] = 0;
}

// ---------------- convert (int64/int32 -> int32) + in-degree histogram fused --------
__global__ void convert_kernel(const void* __restrict__ ei, int E) {
    int i = blockIdx.x * blockDim.x + threadIdx.x;
    if (i >= E) return;
    int r, c;
    if (g_idx64) {
        const long long* p = (const long long*)ei;
        r = (int)p[i];
        c = (int)p[(size_t)E + i];
    } else {
        const int* p = (const int*)ei;
        r = p[i];
        c = p[(size_t)E + i];
    }
    d_row[i] = r;
    d_col[i] = c;
    atomicAdd(&d_cnt[c], 1);
}

// ---------------- multi-block exclusive scan: 3 phases -------------------------------
__global__ __launch_bounds__(SCAN_B) void scan1_kernel(int n) {
    __shared__ int swarp[32];
    int t = threadIdx.x, lane = t & 31, wid = t >> 5;
    int i = blockIdx.x * SCAN_B + t;
    int v = (i < n) ? d_cnt[i] : 0;
    int incl = v;
#pragma unroll
    for (int o = 1; o < 32; o <<= 1) {
        int x = __shfl_up_sync(0xffffffffu, incl, o);
        if (lane >= o) incl += x;
    }
    if (lane == 31) swarp[wid] = incl;
    __syncthreads();
    if (wid == 0) {
        int wv = swarp[lane];
        int winc = wv;
#pragma unroll
        for (int o = 1; o < 32; o <<= 1) {
            int x = __shfl_up_sync(0xffffffffu, winc, o);
            if (lane >= o) winc += x;
        }
        swarp[lane] = winc - wv;
        if (lane == 31) d_bsum[blockIdx.x] = winc;
    }
    __syncthreads();
    if (i < n) d_off[i] = incl - v + swarp[wid];
}

__global__ void scan2_kernel(int nb) {
    __shared__ int swarp[32];
    int t = threadIdx.x, lane = t & 31, wid = t >> 5; // 256 threads
    int v = (t < nb) ? d_bsum[t] : 0;
    int incl = v;
#pragma unroll
    for (int o = 1; o < 32; o <<= 1) {
        int x = __shfl_up_sync(0xffffffffu, incl, o);
        if (lane >= o) incl += x;
    }
    if (lane == 31) swarp[wid] = incl;
    __syncthreads();
    if (wid == 0) {
        int wv = (lane < 8) ? swarp[lane] : 0;
        int winc = wv;
#pragma unroll
        for (int o = 1; o < 8; o <<= 1) {
            int x = __shfl_up_sync(0xffffffffu, winc, o);
            if (lane >= o) winc += x;
        }
        swarp[lane] = winc - wv;
    }
    __syncthreads();
    if (t < nb) d_bsum[t] = incl - v + swarp[wid];
}

__global__ __launch_bounds__(SCAN_B) void scan3_kernel(int n, int E) {
    int i = blockIdx.x * SCAN_B + threadIdx.x;
    if (i >= n) return;
    int excl = d_off[i] + d_bsum[blockIdx.x];
    d_off[i] = excl;
    d_cur[i] = excl;
    d_dinv[i] = rsqrtf((float)(d_cnt[i] + 1));
    if (i == n - 1) d_off[n] = E;
}

// ---------------- place edges into CSR ----------------------------------------------
__global__ void place_kernel(int E) {
    int i = blockIdx.x * blockDim.x + threadIdx.x;
    if (i >= E) return;
    int pos = atomicAdd(&d_cur[d_col[i]], 1);
    d_srcs[pos] = d_row[i];
}

// ---------------- GEMM: C[i,:] = act( (A[i,:] @ W)*(SCALE?dinv[i]:1) + (BIAS?b:0) ) --
template<int K, int NC, bool RELU, bool BIAS, bool SCALE, int R>
__global__ __launch_bounds__(256) void gemm_kernel(
    const float* __restrict__ A, const float* __restrict__ W,
    const float* __restrict__ bias, float* __restrict__ C, int nrows) {
    constexpr int CG  = NC / 16;
    constexpr int RPB = (256 / CG) * R;
    __shared__ float Ws[K * NC];
    for (int t = threadIdx.x; t < K * NC / 4; t += 256)
        ((float4*)Ws)[t] = ((const float4*)W)[t];
    __syncthreads();

    int rg = threadIdx.x / CG;
    int cg = threadIdx.x % CG;
    int r0 = blockIdx.x * RPB + rg * R;

    const float4* Arow[R];
    bool valid[R];
#pragma unroll
    for (int i = 0; i < R; ++i) {
        int r = r0 + i;
        valid[i] = (r < nrows);
        Arow[i] = (const float4*)(A + (size_t)(valid[i] ? r : 0) * K);
    }

    unsigned long long acc[R][8];
#pragma unroll
    for (int i = 0; i < R; ++i)
#pragma unroll
        for (int j = 0; j < 8; ++j) acc[i][j] = 0ull;

#pragma unroll
    for (int k4 = 0; k4 < K / 4; ++k4) {
        float4 a4[R];
#pragma unroll
        for (int i = 0; i < R; ++i) a4[i] = Arow[i][k4];
#pragma unroll
        for (int s = 0; s < 4; ++s) {
            int k = k4 * 4 + s;
            const unsigned long long* w2 =
                (const unsigned long long*)&Ws[k * NC + cg * 16];
            unsigned long long wr[8];
#pragma unroll
            for (int j = 0; j < 8; ++j) wr[j] = w2[j];
#pragma unroll
            for (int i = 0; i < R; ++i) {
                float av = (s == 0) ? a4[i].x : (s == 1) ? a4[i].y
                         : (s == 2) ? a4[i].z : a4[i].w;
                unsigned long long ap = pack2(av);
#pragma unroll
                for (int j = 0; j < 8; ++j) fma2(acc[i][j], ap, wr[j]);
            }
        }
    }

#pragma unroll
    for (int i = 0; i < R; ++i) {
        if (!valid[i]) continue;
        int r = r0 + i;
        float sc = SCALE ? d_dinv[r] : 1.0f;
        float4* Crow = (float4*)(C + (size_t)r * NC + cg * 16);
#pragma unroll
        for (int q = 0; q < 4; ++q) {
            float2 p0 = unpack2(acc[i][q * 2]);
            float2 p1 = unpack2(acc[i][q * 2 + 1]);
            float4 o = make_float4(p0.x * sc, p0.y * sc, p1.x * sc, p1.y * sc);
            if (BIAS) {
                const float4 bb = *(const float4*)&bias[cg * 16 + q * 4];
                o.x += bb.x; o.y += bb.y; o.z += bb.z; o.w += bb.w;
            }
            if (RELU) {
                o.x = fmaxf(o.x, 0.f); o.y = fmaxf(o.y, 0.f);
                o.z = fmaxf(o.z, 0.f); o.w = fmaxf(o.w, 0.f);
            }
            Crow[q] = o;
        }
    }
}

// ---------------- CSR gather: out[c] = relu(dinv[c]*(sum_in g[r] + g[c]) + b) --------
// One warp per node; each lane owns 2 feature columns (float2); 4-edge unroll for MLP.
__global__ __launch_bounds__(256) void gather_csr_kernel(
    const float* __restrict__ b, float* __restrict__ out, int n) {
    int warp = (blockIdx.x * blockDim.x + threadIdx.x) >> 5;
    if (warp >= n) return;
    int lane = threadIdx.x & 31;
    int start = d_off[warp];
    int end   = d_off[warp + 1];
    int col2  = lane * 2;

    float2 acc0 = make_float2(0.f, 0.f), acc1 = make_float2(0.f, 0.f);
    int p = start;
    for (; p + 3 < end; p += 4) {
        int r0 = d_srcs[p];
        int r1 = d_srcs[p + 1];
        int r2 = d_srcs[p + 2];
        int r3 = d_srcs[p + 3];
        float2 v0 = __ldcg((const float2*)&d_g[(size_t)r0 * HID + col2]);
        float2 v1 = __ldcg((const float2*)&d_g[(size_t)r1 * HID + col2]);
        float2 v2 = __ldcg((const float2*)&d_g[(size_t)r2 * HID + col2]);
        float2 v3 = __ldcg((const float2*)&d_g[(size_t)r3 * HID + col2]);
        acc0.x += v0.x; acc0.y += v0.y;
        acc1.x += v1.x; acc1.y += v1.y;
        acc0.x += v2.x; acc0.y += v2.y;
        acc1.x += v3.x; acc1.y += v3.y;
    }
    for (; p < end; ++p) {
        int r0 = d_srcs[p];
        float2 v0 = __ldcg((const float2*)&d_g[(size_t)r0 * HID + col2]);
        acc0.x += v0.x; acc0.y += v0.y;
    }
    // self loop + epilogue
    float2 gs = *(const float2*)&d_g[(size_t)warp * HID + col2];
    float di = d_dinv[warp];
    float2 bb = *(const float2*)&b[col2];
    float2 o;
    o.x = fmaxf(di * (acc0.x + acc1.x + gs.x) + bb.x, 0.f);
    o.y = fmaxf(di * (acc0.y + acc1.y + gs.y) + bb.y, 0.f);
    *(float2*)&out[(size_t)warp * HID + col2] = o;
}

// ---------------- edge scores: es[e] = dot(nr[row[e]], nr[col[e]]) (2-edge ILP) ------
__global__ void escore_kernel(const float* __restrict__ nr, float* __restrict__ es,
                              int E, int half) {
    int tid = blockIdx.x * blockDim.x + threadIdx.x;
    int e = tid >> 4;
    if (e >= half) return;
    int l = (tid & 15) * 4;
    int r0 = d_row[e], c0 = d_col[e];
    int e1 = e + half;
    bool has2 = (e1 < E);
    int r1 = has2 ? d_row[e1] : 0;
    int c1 = has2 ? d_col[e1] : 0;
    float4 a0 = __ldcg((const float4*)&nr[(size_t)r0 * HID + l]);
    float4 b0 = __ldcg((const float4*)&nr[(size_t)c0 * HID + l]);
    float4 a1, b1;
    if (has2) {
        a1 = __ldcg((const float4*)&nr[(size_t)r1 * HID + l]);
        b1 = __ldcg((const float4*)&nr[(size_t)c1 * HID + l]);
    }
    float s0 = a0.x * b0.x + a0.y * b0.y + a0.z * b0.z + a0.w * b0.w;
    float s1 = has2 ? (a1.x * b1.x + a1.y * b1.y + a1.z * b1.z + a1.w * b1.w) : 0.f;
#pragma unroll
    for (int m = 8; m >= 1; m >>= 1) {
        s0 += __shfl_xor_sync(0xffffffffu, s0, m);
        s1 += __shfl_xor_sync(0xffffffffu, s1, m);
    }
    if ((tid & 15) == 0) {
        es[e] = s0;
        if (has2) es[e1] = s1;
    }
}

// ---------------- launch ----------------
extern "C" void kernel_launch(void* const* d_in, const int* in_sizes, int n_in,
                              void* d_out, int out_size) {
    const float* x   = (const float*)d_in[0];
    const void*  ei  = d_in[1];
    const float* W1  = (const float*)d_in[2];
    const float* b1  = (const float*)d_in[3];
    const float* W2  = (const float*)d_in[4];
    const float* b2  = (const float*)d_in[5];
    const float* Wd1 = (const float*)d_in[6];
    const float* bd1 = (const float*)d_in[7];
    const float* Wd2 = (const float*)d_in[8];
    const float* bd2 = (const float*)d_in[9];
    float* out = (float*)d_out;

    int Nn = in_sizes[0] / INCH; // 100000
    int Ee = in_sizes[1] / 2;    // 3200000
    int half = (Ee + 1) / 2;

    float* out_rx = out;
    float* out_es = out + (size_t)Nn * INCH;
    float* out_nr = out_es + (size_t)Ee;

    float *pg = nullptr, *ph = nullptr;
    cudaGetSymbolAddress((void**)&pg, d_g);
    cudaGetSymbolAddress((void**)&ph, d_h);

    const int T = 256;
    int ebl   = (Ee + T - 1) / T;
    int nbl   = (Nn + T - 1) / T;
    int h16bl = (int)(((size_t)half * 16 + T - 1) / T);
    int nwbl  = (int)(((size_t)Nn * 32 + T - 1) / T); // warp per node
    int sbl   = (Nn + SCAN_B - 1) / SCAN_B;           // scan blocks (98)

    cudaStream_t main0 = 0;
    cudaStream_t side = g_ctx.side;

    // preprocessing: convert+histogram -> 3-phase scan
    detect_kernel<<<1, 32, 0, main0>>>((const unsigned*)ei);
    init_cnt_kernel<<<nbl, T, 0, main0>>>(Nn);
    convert_kernel<<<ebl, T, 0, main0>>>(ei, Ee);
    scan1_kernel<<<sbl, SCAN_B, 0, main0>>>(Nn);
    scan2_kernel<<<1, 256, 0, main0>>>(sbl);
    scan3_kernel<<<sbl, SCAN_B, 0, main0>>>(Nn, Ee);

    // fork: place (side) overlaps gemm1 (main) — both only need scan3 results
    cudaEventRecord(g_ctx.evA, main0);
    cudaStreamWaitEvent(side, g_ctx.evA, 0);
    place_kernel<<<ebl, T, 0, side>>>(Ee);
    cudaEventRecord(g_ctx.evB, side);

    // ---- layer 1: g = (x@W1)*dinv (independent of place)
    gemm_kernel<INCH, HID, false, false, true, 4>
        <<<(Nn + 255) / 256, T, 0, main0>>>(x, W1, nullptr, pg, Nn);
    cudaStreamWaitEvent(main0, g_ctx.evB, 0);  // join: gather needs CSR
    gather_csr_kernel<<<nwbl, T, 0, main0>>>(b1, ph, Nn);

    // ---- layer 2 -> node_representation (written straight into out segment)
    gemm_kernel<HID, HID, false, false, true, 4>
        <<<(Nn + 255) / 256, T, 0, main0>>>(ph, W2, nullptr, pg, Nn);
    gather_csr_kernel<<<nwbl, T, 0, main0>>>(b2, out_nr, Nn);

    // fork: escore (side) overlaps decoder GEMMs (main) — both only need out_nr
    cudaEventRecord(g_ctx.evC, main0);
    cudaStreamWaitEvent(side, g_ctx.evC, 0);
    escore_kernel<<<h16bl, T, 0, side>>>(out_nr, out_es, Ee, half);
    cudaEventRecord(g_ctx.evD, side);

    // ---- decoder: rec = relu(nr@Wd1+bd1) ; rx = rec@Wd2 + bd2
    gemm_kernel<HID, HID, true, true, false, 4>
        <<<(Nn + 255) / 256, T, 0, main0>>>(out_nr, Wd1, bd1, ph, Nn);
    gemm_kernel<HID, INCH, false, true, false, 4>
        <<<(Nn + 127) / 128, T, 0, main0>>>(ph, Wd2, bd2, out_rx, Nn);

    // join: everything back on the main stream before harness reads d_out
    cudaStreamWaitEvent(main0, g_ctx.evD, 0);
}

// round 9
// speedup vs baseline: 1.1376x; 1.0152x over previous
#include <cuda_runtime.h>

#define NNODES 100000
#define NEDGES 3200000
#define INCH 128
#define HID 64
#define SCAN_B 1024

// ---------------- scratch (static device globals; no allocs allowed) ----------------
__device__ float d_g[(size_t)NNODES * HID];    // features (gather source)
__device__ float d_h[(size_t)NNODES * HID];    // layer intermediate
__device__ float d_dinv[NNODES];
__device__ int   d_cnt[NNODES];                // in-degree (excl self loop)
__device__ int   d_off[NNODES + 1];            // CSR offsets
__device__ int   d_cur[NNODES];                // placement cursors
__device__ int   d_bsum[256];                  // per-block scan partials
__device__ int   d_srcs[NEDGES];               // CSR: source node per incoming edge
__device__ int   g_idx64;

// ---------------- side stream + events for fork/join (created once, host-side) ------
struct SideCtx {
    cudaStream_t side;
    cudaEvent_t evA, evS, evB, evC, evD;
    SideCtx() {
        cudaStreamCreateWithFlags(&side, cudaStreamNonBlocking);
        cudaEventCreateWithFlags(&evA, cudaEventDisableTiming);
        cudaEventCreateWithFlags(&evS, cudaEventDisableTiming);
        cudaEventCreateWithFlags(&evB, cudaEventDisableTiming);
        cudaEventCreateWithFlags(&evC, cudaEventDisableTiming);
        cudaEventCreateWithFlags(&evD, cudaEventDisableTiming);
    }
};
static SideCtx g_ctx;

// ---------------- helpers ----------------
__device__ __forceinline__ unsigned long long pack2(float v) {
    unsigned long long r;
    asm("mov.b64 %0, {%1, %1};" : "=l"(r) : "f"(v));
    return r;
}
__device__ __forceinline__ void fma2(unsigned long long& acc, unsigned long long a,
                                     unsigned long long b) {
    asm("fma.rn.f32x2 %0, %1, %2, %0;" : "+l"(acc) : "l"(a), "l"(b));
}
__device__ __forceinline__ float2 unpack2(unsigned long long v) {
    float2 r;
    asm("mov.b64 {%0, %1}, %2;" : "=f"(r.x), "=f"(r.y) : "l"(v));
    return r;
}
__device__ __forceinline__ void decode_edge(const void* ei, int E, int i,
                                            int& r, int& c) {
    if (g_idx64) {
        const long long* p = (const long long*)ei;
        r = (int)p[i];
        c = (int)p[(size_t)E + i];
    } else {
        const int* p = (const int*)ei;
        r = p[i];
        c = p[(size_t)E + i];
    }
}
__device__ __forceinline__ int decode_col(const void* ei, int E, int i) {
    if (g_idx64) return (int)((const long long*)ei)[(size_t)E + i];
    return ((const int*)ei)[(size_t)E + i];
}

// ---------------- dtype detection: int64 edge_index has zero high words --------------
__global__ void detect_kernel(const unsigned* __restrict__ ei) {
    unsigned v = 0;
    int i = threadIdx.x;
#pragma unroll
    for (int s = 0; s < 4; ++s) v |= ei[(size_t)(i * 4 + s) * 2 + 1];
    unsigned any = __ballot_sync(0xffffffffu, v != 0);
    if (threadIdx.x == 0) g_idx64 = (any == 0) ? 1 : 0;
}

__global__ void init_cnt_kernel(int n) {
    int i = blockIdx.x * blockDim.x + threadIdx.x;
    if (i < n) d_cnt[i] = 0;
}

// ---------------- in-degree histogram (inline decode) -------------------------------
__global__ void hist_kernel(const void* __restrict__ ei, int E) {
    int i = blockIdx.x * blockDim.x + threadIdx.x;
    if (i >= E) return;
    atomicAdd(&d_cnt[decode_col(ei, E, i)], 1);
}

// ---------------- multi-block exclusive scan: 3 phases -------------------------------
__global__ __launch_bounds__(SCAN_B) void scan1_kernel(int n) {
    __shared__ int swarp[32];
    int t = threadIdx.x, lane = t & 31, wid = t >> 5;
    int i = blockIdx.x * SCAN_B + t;
    int v = (i < n) ? d_cnt[i] : 0;
    int incl = v;
#pragma unroll
    for (int o = 1; o < 32; o <<= 1) {
        int x = __shfl_up_sync(0xffffffffu, incl, o);
        if (lane >= o) incl += x;
    }
    if (lane == 31) swarp[wid] = incl;
    __syncthreads();
    if (wid == 0) {
        int wv = swarp[lane];
        int winc = wv;
#pragma unroll
        for (int o = 1; o < 32; o <<= 1) {
            int x = __shfl_up_sync(0xffffffffu, winc, o);
            if (lane >= o) winc += x;
        }
        swarp[lane] = winc - wv;
        if (lane == 31) d_bsum[blockIdx.x] = winc;
    }
    __syncthreads();
    if (i < n) d_off[i] = incl - v + swarp[wid];
}

__global__ void scan2_kernel(int nb) {
    __shared__ int swarp[32];
    int t = threadIdx.x, lane = t & 31, wid = t >> 5; // 256 threads
    int v = (t < nb) ? d_bsum[t] : 0;
    int incl = v;
#pragma unroll
    for (int o = 1; o < 32; o <<= 1) {
        int x = __shfl_up_sync(0xffffffffu, incl, o);
        if (lane >= o) incl += x;
    }
    if (lane == 31) swarp[wid] = incl;
    __syncthreads();
    if (wid == 0) {
        int wv = (lane < 8) ? swarp[lane] : 0;
        int winc = wv;
#pragma unroll
        for (int o = 1; o < 8; o <<= 1) {
            int x = __shfl_up_sync(0xffffffffu, winc, o);
            if (lane >= o) winc += x;
        }
        swarp[lane] = winc - wv;
    }
    __syncthreads();
    if (t < nb) d_bsum[t] = incl - v + swarp[wid];
}

__global__ __launch_bounds__(SCAN_B) void scan3_kernel(int n, int E) {
    int i = blockIdx.x * SCAN_B + threadIdx.x;
    if (i >= n) return;
    int excl = d_off[i] + d_bsum[blockIdx.x];
    d_off[i] = excl;
    d_cur[i] = excl;
    d_dinv[i] = rsqrtf((float)(d_cnt[i] + 1));
    if (i == n - 1) d_off[n] = E;
}

// ---------------- place edges into CSR (inline decode) ------------------------------
__global__ void place_kernel(const void* __restrict__ ei, int E) {
    int i = blockIdx.x * blockDim.x + threadIdx.x;
    if (i >= E) return;
    int r, c;
    decode_edge(ei, E, i, r, c);
    int pos = atomicAdd(&d_cur[c], 1);
    d_srcs[pos] = r;
}

// ---------------- scale g rows by dinv (post-gemm1, post-scan) ----------------------
__global__ void scale_g_kernel(int n) {
    int idx = blockIdx.x * blockDim.x + threadIdx.x; // over n*16 float4 groups
    if (idx >= n * 16) return;
    float di = d_dinv[idx >> 4];
    float4* p = (float4*)&d_g[(size_t)idx * 4];
    float4 v = *p;
    v.x *= di; v.y *= di; v.z *= di; v.w *= di;
    *p = v;
}

// ---------------- GEMM: C[i,:] = act( (A[i,:] @ W)*(SCALE?dinv[i]:1) + (BIAS?b:0) ) --
template<int K, int NC, bool RELU, bool BIAS, bool SCALE, int R>
__global__ __launch_bounds__(256) void gemm_kernel(
    const float* __restrict__ A, const float* __restrict__ W,
    const float* __restrict__ bias, float* __restrict__ C, int nrows) {
    constexpr int CG  = NC / 16;
    constexpr int RPB = (256 / CG) * R;
    __shared__ float Ws[K * NC];
    for (int t = threadIdx.x; t < K * NC / 4; t += 256)
        ((float4*)Ws)[t] = ((const float4*)W)[t];
    __syncthreads();

    int rg = threadIdx.x / CG;
    int cg = threadIdx.x % CG;
    int r0 = blockIdx.x * RPB + rg * R;

    const float4* Arow[R];
    bool valid[R];
#pragma unroll
    for (int i = 0; i < R; ++i) {
        int r = r0 + i;
        valid[i] = (r < nrows);
        Arow[i] = (const float4*)(A + (size_t)(valid[i] ? r : 0) * K);
    }

    unsigned long long acc[R][8];
#pragma unroll
    for (int i = 0; i < R; ++i)
#pragma unroll
        for (int j = 0; j < 8; ++j) acc[i][j] = 0ull;

#pragma unroll
    for (int k4 = 0; k4 < K / 4; ++k4) {
        float4 a4[R];
#pragma unroll
        for (int i = 0; i < R; ++i) a4[i] = Arow[i][k4];
#pragma unroll
        for (int s = 0; s < 4; ++s) {
            int k = k4 * 4 + s;
            const unsigned long long* w2 =
                (const unsigned long long*)&Ws[k * NC + cg * 16];
            unsigned long long wr[8];
#pragma unroll
            for (int j = 0; j < 8; ++j) wr[j] = w2[j];
#pragma unroll
            for (int i = 0; i < R; ++i) {
                float av = (s == 0) ? a4[i].x : (s == 1) ? a4[i].y
                         : (s == 2) ? a4[i].z : a4[i].w;
                unsigned long long ap = pack2(av);
#pragma unroll
                for (int j = 0; j < 8; ++j) fma2(acc[i][j], ap, wr[j]);
            }
        }
    }

#pragma unroll
    for (int i = 0; i < R; ++i) {
        if (!valid[i]) continue;
        int r = r0 + i;
        float sc = SCALE ? d_dinv[r] : 1.0f;
        float4* Crow = (float4*)(C + (size_t)r * NC + cg * 16);
#pragma unroll
        for (int q = 0; q < 4; ++q) {
            float2 p0 = unpack2(acc[i][q * 2]);
            float2 p1 = unpack2(acc[i][q * 2 + 1]);
            float4 o = make_float4(p0.x * sc, p0.y * sc, p1.x * sc, p1.y * sc);
            if (BIAS) {
                const float4 bb = *(const float4*)&bias[cg * 16 + q * 4];
                o.x += bb.x; o.y += bb.y; o.z += bb.z; o.w += bb.w;
            }
            if (RELU) {
                o.x = fmaxf(o.x, 0.f); o.y = fmaxf(o.y, 0.f);
                o.z = fmaxf(o.z, 0.f); o.w = fmaxf(o.w, 0.f);
            }
            Crow[q] = o;
        }
    }
}

// ---------------- CSR gather: out[c] = relu(dinv[c]*(sum_in g[r] + g[c]) + b) --------
// One warp per node; each lane owns 2 feature columns (float2); 4-edge unroll for MLP.
__global__ __launch_bounds__(256) void gather_csr_kernel(
    const float* __restrict__ b, float* __restrict__ out, int n) {
    int warp = (blockIdx.x * blockDim.x + threadIdx.x) >> 5;
    if (warp >= n) return;
    int lane = threadIdx.x & 31;
    int start = d_off[warp];
    int end   = d_off[warp + 1];
    int col2  = lane * 2;

    float2 acc0 = make_float2(0.f, 0.f), acc1 = make_float2(0.f, 0.f);
    int p = start;
    for (; p + 3 < end; p += 4) {
        int r0 = d_srcs[p];
        int r1 = d_srcs[p + 1];
        int r2 = d_srcs[p + 2];
        int r3 = d_srcs[p + 3];
        float2 v0 = __ldcg((const float2*)&d_g[(size_t)r0 * HID + col2]);
        float2 v1 = __ldcg((const float2*)&d_g[(size_t)r1 * HID + col2]);
        float2 v2 = __ldcg((const float2*)&d_g[(size_t)r2 * HID + col2]);
        float2 v3 = __ldcg((const float2*)&d_g[(size_t)r3 * HID + col2]);
        acc0.x += v0.x; acc0.y += v0.y;
        acc1.x += v1.x; acc1.y += v1.y;
        acc0.x += v2.x; acc0.y += v2.y;
        acc1.x += v3.x; acc1.y += v3.y;
    }
    for (; p < end; ++p) {
        int r0 = d_srcs[p];
        float2 v0 = __ldcg((const float2*)&d_g[(size_t)r0 * HID + col2]);
        acc0.x += v0.x; acc0.y += v0.y;
    }
    // self loop + epilogue
    float2 gs = *(const float2*)&d_g[(size_t)warp * HID + col2];
    float di = d_dinv[warp];
    float2 bb = *(const float2*)&b[col2];
    float2 o;
    o.x = fmaxf(di * (acc0.x + acc1.x + gs.x) + bb.x, 0.f);
    o.y = fmaxf(di * (acc0.y + acc1.y + gs.y) + bb.y, 0.f);
    *(float2*)&out[(size_t)warp * HID + col2] = o;
}

// ---------------- edge scores: es[e] = dot(nr[row[e]], nr[col[e]]) (2-edge ILP) ------
__global__ void escore_kernel(const void* __restrict__ ei,
                              const float* __restrict__ nr, float* __restrict__ es,
                              int E, int half) {
    int tid = blockIdx.x * blockDim.x + threadIdx.x;
    int e = tid >> 4;
    if (e >= half) return;
    int l = (tid & 15) * 4;
    int r0, c0, r1 = 0, c1 = 0;
    decode_edge(ei, E, e, r0, c0);
    int e1 = e + half;
    bool has2 = (e1 < E);
    if (has2) decode_edge(ei, E, e1, r1, c1);
    float4 a0 = __ldcg((const float4*)&nr[(size_t)r0 * HID + l]);
    float4 b0 = __ldcg((const float4*)&nr[(size_t)c0 * HID + l]);
    float4 a1, b1;
    if (has2) {
        a1 = __ldcg((const float4*)&nr[(size_t)r1 * HID + l]);
        b1 = __ldcg((const float4*)&nr[(size_t)c1 * HID + l]);
    }
    float s0 = a0.x * b0.x + a0.y * b0.y + a0.z * b0.z + a0.w * b0.w;
    float s1 = has2 ? (a1.x * b1.x + a1.y * b1.y + a1.z * b1.z + a1.w * b1.w) : 0.f;
#pragma unroll
    for (int m = 8; m >= 1; m >>= 1) {
        s0 += __shfl_xor_sync(0xffffffffu, s0, m);
        s1 += __shfl_xor_sync(0xffffffffu, s1, m);
    }
    if ((tid & 15) == 0) {
        es[e] = s0;
        if (has2) es[e1] = s1;
    }
}

// ---------------- launch ----------------
extern "C" void kernel_launch(void* const* d_in, const int* in_sizes, int n_in,
                              void* d_out, int out_size) {
    const float* x   = (const float*)d_in[0];
    const void*  ei  = d_in[1];
    const float* W1  = (const float*)d_in[2];
    const float* b1  = (const float*)d_in[3];
    const float* W2  = (const float*)d_in[4];
    const float* b2  = (const float*)d_in[5];
    const float* Wd1 = (const float*)d_in[6];
    const float* bd1 = (const float*)d_in[7];
    const float* Wd2 = (const float*)d_in[8];
    const float* bd2 = (const float*)d_in[9];
    float* out = (float*)d_out;

    int Nn = in_sizes[0] / INCH; // 100000
    int Ee = in_sizes[1] / 2;    // 3200000
    int half = (Ee + 1) / 2;

    float* out_rx = out;
    float* out_es = out + (size_t)Nn * INCH;
    float* out_nr = out_es + (size_t)Ee;

    float *pg = nullptr, *ph = nullptr;
    cudaGetSymbolAddress((void**)&pg, d_g);
    cudaGetSymbolAddress((void**)&ph, d_h);

    const int T = 256;
    int ebl   = (Ee + T - 1) / T;
    int nbl   = (Nn + T - 1) / T;
    int h16bl = (int)(((size_t)half * 16 + T - 1) / T);
    int n16bl = (int)(((size_t)Nn * 16 + T - 1) / T);
    int nwbl  = (int)(((size_t)Nn * 32 + T - 1) / T); // warp per node
    int sbl   = (Nn + SCAN_B - 1) / SCAN_B;           // scan blocks (98)

    cudaStream_t main0 = 0;
    cudaStream_t side = g_ctx.side;

    // detect dtype first (needed by hist/place/escore)
    detect_kernel<<<1, 32, 0, main0>>>((const unsigned*)ei);

    // fork: full preprocessing chain on side stream, gemm1 (unscaled) on main
    cudaEventRecord(g_ctx.evA, main0);
    cudaStreamWaitEvent(side, g_ctx.evA, 0);
    init_cnt_kernel<<<nbl, T, 0, side>>>(Nn);
    hist_kernel<<<ebl, T, 0, side>>>(ei, Ee);
    scan1_kernel<<<sbl, SCAN_B, 0, side>>>(Nn);
    scan2_kernel<<<1, 256, 0, side>>>(sbl);
    scan3_kernel<<<sbl, SCAN_B, 0, side>>>(Nn, Ee);
    cudaEventRecord(g_ctx.evS, side);      // dinv + offsets ready
    place_kernel<<<ebl, T, 0, side>>>(ei, Ee);
    cudaEventRecord(g_ctx.evB, side);      // CSR ready

    // ---- layer 1: g' = x@W1 (no dinv needed -> overlaps preprocessing)
    gemm_kernel<INCH, HID, false, false, false, 4>
        <<<(Nn + 255) / 256, T, 0, main0>>>(x, W1, nullptr, pg, Nn);
    cudaStreamWaitEvent(main0, g_ctx.evS, 0);
    scale_g_kernel<<<n16bl, T, 0, main0>>>(Nn);      // g = g' * dinv
    cudaStreamWaitEvent(main0, g_ctx.evB, 0);
    gather_csr_kernel<<<nwbl, T, 0, main0>>>(b1, ph, Nn);

    // ---- layer 2 -> node_representation (written straight into out segment)
    gemm_kernel<HID, HID, false, false, true, 4>
        <<<(Nn + 255) / 256, T, 0, main0>>>(ph, W2, nullptr, pg, Nn);
    gather_csr_kernel<<<nwbl, T, 0, main0>>>(b2, out_nr, Nn);

    // fork: escore (side) overlaps decoder GEMMs (main) — both only need out_nr
    cudaEventRecord(g_ctx.evC, main0);
    cudaStreamWaitEvent(side, g_ctx.evC, 0);
    escore_kernel<<<h16bl, T, 0, side>>>(ei, out_nr, out_es, Ee, half);
    cudaEventRecord(g_ctx.evD, side);

    // ---- decoder: rec = relu(nr@Wd1+bd1) ; rx = rec@Wd2 + bd2
    gemm_kernel<HID, HID, true, true, false, 4>
        <<<(Nn + 255) / 256, T, 0, main0>>>(out_nr, Wd1, bd1, ph, Nn);
    gemm_kernel<HID, INCH, false, true, false, 4>
        <<<(Nn + 127) / 128, T, 0, main0>>>(ph, Wd2, bd2, out_rx, Nn);

    // join: everything back on the main stream before harness reads d_out
    cudaStreamWaitEvent(main0, g_ctx.evD, 0);
}